// round 6
// baseline (speedup 1.0000x reference)
#include <cuda_runtime.h>
#include <math.h>

#define NOBJ 256
#define CCLS 151
#define DH   512
#define GW   2048          // G width: [weff3 | weff4(w4w) | weff5(w5w) | w3u]
#define TSTEPS 3

// ---------------- device scratch ----------------
__device__ float g_h[NOBJ * DH];
__device__ float g_weff[3][DH * DH];
__device__ float g_G[NOBJ * GW];
__device__ float g_vpart[4][GW];        // per-m-tile column sums of G
__device__ float g_zv[NOBJ * DH];
__device__ float g_rvh[NOBJ * DH];
__device__ float g_part[4][NOBJ * DH];  // K-split partials
__device__ float g_out2[NOBJ * DH];
__device__ float g_wcred[CCLS * DH];
__device__ float g_pc[8][NOBJ * 160];   // classifier K-split partials (ldc=160)
__device__ unsigned g_bar;

__global__ void k_reset() { g_bar = 0u; }

// ---------------- f32x2 helpers ----------------
__device__ __forceinline__ unsigned long long f2pack(float lo, float hi) {
    unsigned long long r;
    asm("mov.b64 %0, {%1, %2};" : "=l"(r) : "r"(__float_as_uint(lo)), "r"(__float_as_uint(hi)));
    return r;
}
__device__ __forceinline__ void ffma2(unsigned long long& d, unsigned long long a, unsigned long long b) {
    asm("fma.rn.f32x2 %0, %1, %2, %0;" : "+l"(d) : "l"(a), "l"(b));
}
__device__ __forceinline__ float2 f2unpack(unsigned long long v) {
    unsigned lo, hi;
    asm("mov.b64 {%0, %1}, %2;" : "=r"(lo), "=r"(hi) : "l"(v));
    return make_float2(__uint_as_float(lo), __uint_as_float(hi));
}

__device__ __forceinline__ float sigmoidf_(float x) { return 1.f / (1.f + __expf(-x)); }
__device__ __forceinline__ float tanhf_(float x) { return 1.f - 2.f / (__expf(2.f * x) + 1.f); }

// ---------------- global barrier ----------------
__device__ __forceinline__ void gsync(unsigned& epoch, int nb) {
    __syncthreads();
    if (threadIdx.x == 0) {
        __threadfence();
        atomicAdd(&g_bar, 1u);
        epoch += (unsigned)nb;
        while (*(volatile unsigned*)&g_bar < epoch) { __nanosleep(64); }
        __threadfence();
    }
    __syncthreads();
}

// ---------------- 64x64 tile GEMM: C = A[64,kLen] @ W[nValid,kLen]^T ----------------
// k-pair interleaved smem layout: buf[k2][m][2] so (k,k+1) pairs load as 64-bit lanes.
// Double buffered, global prefetch overlapped with compute. One sync per 32-k chunk.
// sm layout (floats): A bufs at [0, 2048), [2048, 4096); W bufs at [4096+...]
__device__ __forceinline__ void gemm_tile(
    const float* __restrict__ A, int lda,
    const float* __restrict__ W, int ldw,
    int kLen, int nValid,
    float* __restrict__ C, int ldc,
    float* __restrict__ vout,
    float* __restrict__ sm)
{
    const int tid = threadIdx.x;
    const int tx = tid & 15, ty = tid >> 4;
    const int row = tid & 63, kq = tid >> 6;       // kq in 0..3
    const float* Arow = A + row * lda;
    const float* Wrow = W + row * ldw;
    const bool wok = row < nValid;
    const int nCh = kLen >> 5;

    unsigned long long acc[4][4];
    #pragma unroll
    for (int i = 0; i < 4; i++)
        #pragma unroll
        for (int j = 0; j < 4; j++) acc[i][j] = 0ull;

    const float4 z4 = make_float4(0.f, 0.f, 0.f, 0.f);
    float4 pa0, pa1, pw0, pw1;

    // prefetch chunk 0
    pa0 = *(const float4*)(Arow + kq * 4);
    pa1 = *(const float4*)(Arow + 16 + kq * 4);
    pw0 = wok ? *(const float4*)(Wrow + kq * 4) : z4;
    pw1 = wok ? *(const float4*)(Wrow + 16 + kq * 4) : z4;

    // store chunk 0 into buffer 0
    {
        float* a = sm;
        float* w = sm + 4096;
        int r2 = row * 2;
        *(float2*)&a[(kq * 2    ) * 128 + r2] = make_float2(pa0.x, pa0.y);
        *(float2*)&a[(kq * 2 + 1) * 128 + r2] = make_float2(pa0.z, pa0.w);
        *(float2*)&a[(kq * 2 + 8) * 128 + r2] = make_float2(pa1.x, pa1.y);
        *(float2*)&a[(kq * 2 + 9) * 128 + r2] = make_float2(pa1.z, pa1.w);
        *(float2*)&w[(kq * 2    ) * 128 + r2] = make_float2(pw0.x, pw0.y);
        *(float2*)&w[(kq * 2 + 1) * 128 + r2] = make_float2(pw0.z, pw0.w);
        *(float2*)&w[(kq * 2 + 8) * 128 + r2] = make_float2(pw1.x, pw1.y);
        *(float2*)&w[(kq * 2 + 9) * 128 + r2] = make_float2(pw1.z, pw1.w);
    }
    __syncthreads();

    int buf = 0;
    for (int c = 0; c < nCh; c++) {
        // prefetch next chunk (global -> regs), overlapped with compute below
        if (c + 1 < nCh) {
            const float* Ac = Arow + (c + 1) * 32;
            const float* Wc = Wrow + (c + 1) * 32;
            pa0 = *(const float4*)(Ac + kq * 4);
            pa1 = *(const float4*)(Ac + 16 + kq * 4);
            pw0 = wok ? *(const float4*)(Wc + kq * 4) : z4;
            pw1 = wok ? *(const float4*)(Wc + 16 + kq * 4) : z4;
        }
        const float* a = sm + buf * 2048;
        const float* w = sm + 4096 + buf * 2048;
        #pragma unroll
        for (int k2 = 0; k2 < 16; k2++) {
            float4 av0 = *(const float4*)&a[k2 * 128 + ty * 8];
            float4 av1 = *(const float4*)&a[k2 * 128 + ty * 8 + 4];
            float4 bv0 = *(const float4*)&w[k2 * 128 + tx * 8];
            float4 bv1 = *(const float4*)&w[k2 * 128 + tx * 8 + 4];
            unsigned long long ap0 = f2pack(av0.x, av0.y), ap1 = f2pack(av0.z, av0.w);
            unsigned long long ap2 = f2pack(av1.x, av1.y), ap3 = f2pack(av1.z, av1.w);
            unsigned long long bp0 = f2pack(bv0.x, bv0.y), bp1 = f2pack(bv0.z, bv0.w);
            unsigned long long bp2 = f2pack(bv1.x, bv1.y), bp3 = f2pack(bv1.z, bv1.w);
            ffma2(acc[0][0], ap0, bp0); ffma2(acc[0][1], ap0, bp1);
            ffma2(acc[0][2], ap0, bp2); ffma2(acc[0][3], ap0, bp3);
            ffma2(acc[1][0], ap1, bp0); ffma2(acc[1][1], ap1, bp1);
            ffma2(acc[1][2], ap1, bp2); ffma2(acc[1][3], ap1, bp3);
            ffma2(acc[2][0], ap2, bp0); ffma2(acc[2][1], ap2, bp1);
            ffma2(acc[2][2], ap2, bp2); ffma2(acc[2][3], ap2, bp3);
            ffma2(acc[3][0], ap3, bp0); ffma2(acc[3][1], ap3, bp1);
            ffma2(acc[3][2], ap3, bp2); ffma2(acc[3][3], ap3, bp3);
        }
        // store prefetched chunk into the other buffer (its old contents are done)
        if (c + 1 < nCh) {
            float* a2 = sm + (buf ^ 1) * 2048;
            float* w2 = sm + 4096 + (buf ^ 1) * 2048;
            int r2 = row * 2;
            *(float2*)&a2[(kq * 2    ) * 128 + r2] = make_float2(pa0.x, pa0.y);
            *(float2*)&a2[(kq * 2 + 1) * 128 + r2] = make_float2(pa0.z, pa0.w);
            *(float2*)&a2[(kq * 2 + 8) * 128 + r2] = make_float2(pa1.x, pa1.y);
            *(float2*)&a2[(kq * 2 + 9) * 128 + r2] = make_float2(pa1.z, pa1.w);
            *(float2*)&w2[(kq * 2    ) * 128 + r2] = make_float2(pw0.x, pw0.y);
            *(float2*)&w2[(kq * 2 + 1) * 128 + r2] = make_float2(pw0.z, pw0.w);
            *(float2*)&w2[(kq * 2 + 8) * 128 + r2] = make_float2(pw1.x, pw1.y);
            *(float2*)&w2[(kq * 2 + 9) * 128 + r2] = make_float2(pw1.z, pw1.w);
        }
        __syncthreads();
        buf ^= 1;
    }

    // reduce k-pairs: c[i][j] = lo + hi
    float cacc[4][4];
    #pragma unroll
    for (int i = 0; i < 4; i++)
        #pragma unroll
        for (int j = 0; j < 4; j++) {
            float2 u = f2unpack(acc[i][j]);
            cacc[i][j] = u.x + u.y;
        }

    #pragma unroll
    for (int i = 0; i < 4; i++) {
        float* crow = C + (ty * 4 + i) * ldc;
        #pragma unroll
        for (int j = 0; j < 4; j++) {
            int n = (tx << 2) + j;
            if (n < nValid) crow[n] = cacc[i][j];
        }
    }

    if (vout) {
        // column sums of the 64x64 tile
        float* red = sm;          // scratch [16][64]
        #pragma unroll
        for (int j = 0; j < 4; j++) {
            float s = cacc[0][j] + cacc[1][j] + cacc[2][j] + cacc[3][j];
            red[ty * 64 + (tx << 2) + j] = s;
        }
        __syncthreads();
        if (tid < 64) {
            float s = 0.f;
            #pragma unroll
            for (int r = 0; r < 16; r++) s += red[r * 64 + tid];
            vout[tid] = s;
        }
        __syncthreads();
    }
}

// ---------------- persistent kernel ----------------
__global__ void __launch_bounds__(256, 1) ggnn_persistent(
    const float* __restrict__ input, const float* __restrict__ matrix,
    const float* __restrict__ w3w, const float* __restrict__ b3w,
    const float* __restrict__ w3u, const float* __restrict__ b3u,
    const float* __restrict__ w4w, const float* __restrict__ b4w,
    const float* __restrict__ w5w, const float* __restrict__ b5w,
    const float* __restrict__ w5u, const float* __restrict__ b5u,
    const float* __restrict__ wo,  const float* __restrict__ bo,
    const float* __restrict__ wc,  const float* __restrict__ bc,
    float* __restrict__ out)
{
    __shared__ __align__(16) float sm[8192];   // 32 KB: double-buffered A/W tiles
    __shared__ float s_red[16];
    __shared__ float s_s1, s_s2;

    const int NB = gridDim.x;
    const int bid = blockIdx.x;
    const int tid = threadIdx.x;
    const int gstride = NB * 256;
    unsigned epoch = 0;

    // ---- s1 (colsum of matrix col 0), s2 (rowsum of matrix row 0) ----
    {
        float a = (tid < CCLS) ? matrix[tid * CCLS] : 0.f;
        float b = (tid < CCLS) ? matrix[tid] : 0.f;
        #pragma unroll
        for (int off = 16; off; off >>= 1) {
            a += __shfl_xor_sync(0xffffffffu, a, off);
            b += __shfl_xor_sync(0xffffffffu, b, off);
        }
        if ((tid & 31) == 0) { s_red[tid >> 5] = a; s_red[8 + (tid >> 5)] = b; }
        __syncthreads();
        if (tid == 0) {
            float sa = 0.f, sb = 0.f;
            #pragma unroll
            for (int w = 0; w < 8; w++) { sa += s_red[w]; sb += s_red[8 + w]; }
            s_s1 = sa; s_s2 = sb;
        }
        __syncthreads();
    }
    const float s1 = s_s1, s2 = s_s2;

    // ---- setup phase ----
    for (int u = bid * 256 + tid; u < 3 * DH * DH / 4; u += gstride) {
        int which = u >> 16;
        int r = u & 65535;
        int o = r >> 7;
        int d4 = (r & 127) << 2;
        const float* w = (which == 0) ? w3w : (which == 1) ? w4w : w5w;
        float4 lo = *(const float4*)(w + o * 2 * DH + d4);
        float4 hi = *(const float4*)(w + o * 2 * DH + DH + d4);
        float4 e;
        e.x = s1 * lo.x + s2 * hi.x; e.y = s1 * lo.y + s2 * hi.y;
        e.z = s1 * lo.z + s2 * hi.z; e.w = s1 * lo.w + s2 * hi.w;
        *(float4*)&g_weff[which][o * DH + d4] = e;
    }
    for (int u = bid * 256 + tid; u < NOBJ * DH / 4; u += gstride)
        ((float4*)g_h)[u] = ((const float4*)input)[u];
    // wcred[c,d] = sum_c2 wc[c, c2*D + d]; unit = (c, d-half)
    for (int unit = bid; unit < CCLS * 2; unit += NB) {
        int c = unit >> 1;
        int d0 = (unit & 1) * 256;
        const float* base = wc + (size_t)c * (CCLS * DH) + d0;
        int d = tid;   // 0..255
        float s = 0.f;
        #pragma unroll 4
        for (int c2 = 0; c2 < CCLS; c2++) s += base[c2 * DH + d];
        g_wcred[c * DH + d0 + d] = s;
    }
    gsync(epoch, NB);

    // ---- T steps ----
    for (int t = 0; t < TSTEPS; t++) {
        // GEMM1: G = h @ [weff0|weff1|weff2|w3u]^T (256 x 2048) + column-sum partials
        for (int tile = bid; tile < 128; tile += NB) {
            int mt = tile & 3, nt = tile >> 2;
            int m0 = mt * 64, n0 = nt * 64;
            int z = n0 >> 9;
            const float* Wp = (z < 3) ? &g_weff[z][(n0 & 511) * DH]
                                      : (w3u + (n0 & 511) * DH);
            gemm_tile(g_h + m0 * DH, DH, Wp, DH, DH, 64,
                      g_G + m0 * GW + n0, GW, &g_vpart[mt][n0], sm);
        }
        gsync(epoch, NB);

        // gate1: zv, rvh
        for (int i = bid * 256 + tid; i < NOBJ * DH; i += gstride) {
            int o = i & (DH - 1);
            float v0 = g_vpart[0][o] + g_vpart[1][o] + g_vpart[2][o] + g_vpart[3][o];
            float v1 = g_vpart[0][512 + o] + g_vpart[1][512 + o] + g_vpart[2][512 + o] + g_vpart[3][512 + o];
            const float* Grow = g_G + (i >> 9) * GW;
            float G0 = Grow[o], G1 = Grow[512 + o], G3 = Grow[1536 + o];
            float bu = b3u[o] + G3;
            float z = sigmoidf_(v0 - G0 + b3w[o] + bu);
            float r = sigmoidf_(v1 - G1 + b4w[o] + bu);
            g_zv[i] = z;
            g_rvh[i] = r * g_h[i];
        }
        gsync(epoch, NB);

        // GEMM2: g5u = rvh @ w5u^T, K-split x4
        for (int tile = bid; tile < 128; tile += NB) {
            int kc = tile & 3, mt = (tile >> 2) & 3, nt = tile >> 4;
            int m0 = mt * 64, n0 = nt * 64, k0 = kc * 128;
            gemm_tile(g_rvh + m0 * DH + k0, DH, w5u + n0 * DH + k0, DH, 128, 64,
                      g_part[kc] + m0 * DH + n0, DH, nullptr, sm);
        }
        gsync(epoch, NB);

        // gate2: h update
        for (int i = bid * 256 + tid; i < NOBJ * DH; i += gstride) {
            int o = i & (DH - 1);
            float v2 = g_vpart[0][1024 + o] + g_vpart[1][1024 + o] + g_vpart[2][1024 + o] + g_vpart[3][1024 + o];
            float G2 = g_G[(i >> 9) * GW + 1024 + o];
            float g5 = g_part[0][i] + g_part[1][i] + g_part[2][i] + g_part[3][i];
            float hv = tanhf_(v2 - G2 + b5w[o] + g5 + b5u[o]);
            float z = g_zv[i];
            g_h[i] = (1.f - z) * g_h[i] + z * hv;
        }
        gsync(epoch, NB);
    }

    // GEMM3: pre-out = h@wo[:,:512]^T + input@wo[:,512:]^T, K-split over 1024
    for (int tile = bid; tile < 128; tile += NB) {
        int kc = tile & 3, mt = (tile >> 2) & 3, nt = tile >> 4;
        int m0 = mt * 64, n0 = nt * 64;
        const float* Ap; const float* Wp;
        if (kc < 2) { Ap = g_h + m0 * DH + kc * 256;        Wp = wo + n0 * (2 * DH) + kc * 256; }
        else        { Ap = input + m0 * DH + (kc - 2) * 256; Wp = wo + n0 * (2 * DH) + 512 + (kc - 2) * 256; }
        gemm_tile(Ap, DH, Wp, 2 * DH, 256, 64,
                  g_part[kc] + m0 * DH + n0, DH, nullptr, sm);
    }
    gsync(epoch, NB);

    // out2 = relu(sum partials + bo)
    for (int i = bid * 256 + tid; i < NOBJ * DH; i += gstride) {
        int o = i & (DH - 1);
        float s = g_part[0][i] + g_part[1][i] + g_part[2][i] + g_part[3][i] + bo[o];
        g_out2[i] = fmaxf(s, 0.f);
    }
    gsync(epoch, NB);

    // GEMM4: out2 @ wcred^T (256 x 151), K-split x8
    for (int tile = bid; tile < 96; tile += NB) {
        int nt = tile % 3; int mt = (tile / 3) & 3; int kc = tile / 12;
        int m0 = mt * 64, n0 = nt * 64, k0 = kc * 64;
        int nv = CCLS - n0; if (nv > 64) nv = 64;
        gemm_tile(g_out2 + m0 * DH + k0, DH, g_wcred + n0 * DH + k0, DH, 64, nv,
                  g_pc[kc] + m0 * 160 + n0, 160, nullptr, sm);
    }
    gsync(epoch, NB);

    // final: out = sum partials + bc
    for (int i = bid * 256 + tid; i < NOBJ * CCLS; i += gstride) {
        int n = i / CCLS, c = i - n * CCLS;
        float s = bc[c];
        #pragma unroll
        for (int kc = 0; kc < 8; kc++) s += g_pc[kc][n * 160 + c];
        out[i] = s;
    }
}

// ---------------- host launcher ----------------
extern "C" void kernel_launch(void* const* d_in, const int* in_sizes, int n_in,
                              void* d_out, int out_size) {
    (void)in_sizes; (void)n_in; (void)out_size;
    const float* input  = (const float*)d_in[0];
    const float* matrix = (const float*)d_in[1];
    const float* w3w = (const float*)d_in[2];
    const float* b3w = (const float*)d_in[3];
    const float* w3u = (const float*)d_in[4];
    const float* b3u = (const float*)d_in[5];
    const float* w4w = (const float*)d_in[6];
    const float* b4w = (const float*)d_in[7];
    // d_in[8] = w4u, d_in[9] = b4u : unused (faithful to reference bug)
    const float* w5w = (const float*)d_in[10];
    const float* b5w = (const float*)d_in[11];
    const float* w5u = (const float*)d_in[12];
    const float* b5u = (const float*)d_in[13];
    const float* wo  = (const float*)d_in[14];
    const float* bo  = (const float*)d_in[15];
    const float* wc  = (const float*)d_in[16];
    const float* bc  = (const float*)d_in[17];
    float* out = (float*)d_out;

    // Residency-proven block count (software barrier must not outnumber resident blocks)
    int sms = 0;
    cudaDeviceGetAttribute(&sms, cudaDevAttrMultiProcessorCount, 0);
    if (sms <= 0) sms = 1;
    int perSM = 0;
    cudaOccupancyMaxActiveBlocksPerMultiprocessor(&perSM, ggnn_persistent, 256, 0);
    if (perSM <= 0) perSM = 1;
    long long cap = (long long)sms * (long long)perSM;
    int NB = (cap < 148) ? (int)cap : 148;
    if (NB < 1) NB = 1;

    k_reset<<<1, 1>>>();
    ggnn_persistent<<<NB, 256>>>(input, matrix, w3w, b3w, w3u, b3u, w4w, b4w,
                                 w5w, b5w, w5u, b5u, wo, bo, wc, bc, out);
}

// round 7
// speedup vs baseline: 1.0344x; 1.0344x over previous
#include <cuda_runtime.h>
#include <math.h>

#define NOBJ 256
#define CCLS 151
#define DH   512
#define GW   2048          // G width: [weff3 | weff4(w4w) | weff5(w5w) | w3u]
#define TSTEPS 3

// ---------------- device scratch ----------------
__device__ float g_h[NOBJ * DH];
__device__ float g_weff[3][DH * DH];
__device__ float g_Gp[2][NOBJ * GW];    // GEMM1 K-split partials
__device__ float g_vpart[8][GW];        // column-sum partials: [kc*4+mt][col]
__device__ float g_zv[NOBJ * DH];
__device__ float g_rvh[NOBJ * DH];
__device__ float g_part[8][NOBJ * DH];  // K-split partials (GEMM2 / GEMM3)
__device__ float g_out2[NOBJ * DH];
__device__ float g_wcred[CCLS * DH];
__device__ float g_pc[8][NOBJ * 160];   // classifier K-split partials (ldc=160)
__device__ unsigned g_bar;

__global__ void k_reset() { g_bar = 0u; }

// ---------------- f32x2 helpers ----------------
__device__ __forceinline__ unsigned long long f2pack(float lo, float hi) {
    unsigned long long r;
    asm("mov.b64 %0, {%1, %2};" : "=l"(r) : "r"(__float_as_uint(lo)), "r"(__float_as_uint(hi)));
    return r;
}
__device__ __forceinline__ void ffma2(unsigned long long& d, unsigned long long a, unsigned long long b) {
    asm("fma.rn.f32x2 %0, %1, %2, %0;" : "+l"(d) : "l"(a), "l"(b));
}
__device__ __forceinline__ float2 f2unpack(unsigned long long v) {
    unsigned lo, hi;
    asm("mov.b64 {%0, %1}, %2;" : "=r"(lo), "=r"(hi) : "l"(v));
    return make_float2(__uint_as_float(lo), __uint_as_float(hi));
}

__device__ __forceinline__ float sigmoidf_(float x) { return 1.f / (1.f + __expf(-x)); }
__device__ __forceinline__ float tanhf_(float x) { return 1.f - 2.f / (__expf(2.f * x) + 1.f); }

// ---------------- global barrier ----------------
__device__ __forceinline__ void gsync(unsigned& epoch, int nb) {
    __syncthreads();
    if (threadIdx.x == 0) {
        __threadfence();
        atomicAdd(&g_bar, 1u);
        epoch += (unsigned)nb;
        while (*(volatile unsigned*)&g_bar < epoch) { __nanosleep(64); }
        __threadfence();
    }
    __syncthreads();
}

// ---------------- 64x64 tile GEMM: C = A[64,kLen] @ W[nValid,kLen]^T ----------------
// k-pair interleaved smem: buf[k2][m][2] so (k,k+1) pairs load as 64-bit lanes.
// Double buffered; one sync per 32-k chunk.
__device__ __forceinline__ void gemm_tile(
    const float* __restrict__ A, int lda,
    const float* __restrict__ W, int ldw,
    int kLen, int nValid,
    float* __restrict__ C, int ldc,
    float* __restrict__ vout,
    float* __restrict__ sm)
{
    const int tid = threadIdx.x;
    const int tx = tid & 15, ty = tid >> 4;
    const int row = tid & 63, kq = tid >> 6;       // kq in 0..3
    const float* Arow = A + row * lda;
    const float* Wrow = W + row * ldw;
    const bool wok = row < nValid;
    const int nCh = kLen >> 5;

    unsigned long long acc[4][4];
    #pragma unroll
    for (int i = 0; i < 4; i++)
        #pragma unroll
        for (int j = 0; j < 4; j++) acc[i][j] = 0ull;

    const float4 z4 = make_float4(0.f, 0.f, 0.f, 0.f);
    float4 pa0, pa1, pw0, pw1;

    pa0 = *(const float4*)(Arow + kq * 4);
    pa1 = *(const float4*)(Arow + 16 + kq * 4);
    pw0 = wok ? *(const float4*)(Wrow + kq * 4) : z4;
    pw1 = wok ? *(const float4*)(Wrow + 16 + kq * 4) : z4;

    {
        float* a = sm;
        float* w = sm + 4096;
        int r2 = row * 2;
        *(float2*)&a[(kq * 2    ) * 128 + r2] = make_float2(pa0.x, pa0.y);
        *(float2*)&a[(kq * 2 + 1) * 128 + r2] = make_float2(pa0.z, pa0.w);
        *(float2*)&a[(kq * 2 + 8) * 128 + r2] = make_float2(pa1.x, pa1.y);
        *(float2*)&a[(kq * 2 + 9) * 128 + r2] = make_float2(pa1.z, pa1.w);
        *(float2*)&w[(kq * 2    ) * 128 + r2] = make_float2(pw0.x, pw0.y);
        *(float2*)&w[(kq * 2 + 1) * 128 + r2] = make_float2(pw0.z, pw0.w);
        *(float2*)&w[(kq * 2 + 8) * 128 + r2] = make_float2(pw1.x, pw1.y);
        *(float2*)&w[(kq * 2 + 9) * 128 + r2] = make_float2(pw1.z, pw1.w);
    }
    __syncthreads();

    int buf = 0;
    for (int c = 0; c < nCh; c++) {
        if (c + 1 < nCh) {
            const float* Ac = Arow + (c + 1) * 32;
            const float* Wc = Wrow + (c + 1) * 32;
            pa0 = *(const float4*)(Ac + kq * 4);
            pa1 = *(const float4*)(Ac + 16 + kq * 4);
            pw0 = wok ? *(const float4*)(Wc + kq * 4) : z4;
            pw1 = wok ? *(const float4*)(Wc + 16 + kq * 4) : z4;
        }
        const float* a = sm + buf * 2048;
        const float* w = sm + 4096 + buf * 2048;
        #pragma unroll
        for (int k2 = 0; k2 < 16; k2++) {
            float4 av0 = *(const float4*)&a[k2 * 128 + ty * 8];
            float4 av1 = *(const float4*)&a[k2 * 128 + ty * 8 + 4];
            float4 bv0 = *(const float4*)&w[k2 * 128 + tx * 8];
            float4 bv1 = *(const float4*)&w[k2 * 128 + tx * 8 + 4];
            unsigned long long ap0 = f2pack(av0.x, av0.y), ap1 = f2pack(av0.z, av0.w);
            unsigned long long ap2 = f2pack(av1.x, av1.y), ap3 = f2pack(av1.z, av1.w);
            unsigned long long bp0 = f2pack(bv0.x, bv0.y), bp1 = f2pack(bv0.z, bv0.w);
            unsigned long long bp2 = f2pack(bv1.x, bv1.y), bp3 = f2pack(bv1.z, bv1.w);
            ffma2(acc[0][0], ap0, bp0); ffma2(acc[0][1], ap0, bp1);
            ffma2(acc[0][2], ap0, bp2); ffma2(acc[0][3], ap0, bp3);
            ffma2(acc[1][0], ap1, bp0); ffma2(acc[1][1], ap1, bp1);
            ffma2(acc[1][2], ap1, bp2); ffma2(acc[1][3], ap1, bp3);
            ffma2(acc[2][0], ap2, bp0); ffma2(acc[2][1], ap2, bp1);
            ffma2(acc[2][2], ap2, bp2); ffma2(acc[2][3], ap2, bp3);
            ffma2(acc[3][0], ap3, bp0); ffma2(acc[3][1], ap3, bp1);
            ffma2(acc[3][2], ap3, bp2); ffma2(acc[3][3], ap3, bp3);
        }
        if (c + 1 < nCh) {
            float* a2 = sm + (buf ^ 1) * 2048;
            float* w2 = sm + 4096 + (buf ^ 1) * 2048;
            int r2 = row * 2;
            *(float2*)&a2[(kq * 2    ) * 128 + r2] = make_float2(pa0.x, pa0.y);
            *(float2*)&a2[(kq * 2 + 1) * 128 + r2] = make_float2(pa0.z, pa0.w);
            *(float2*)&a2[(kq * 2 + 8) * 128 + r2] = make_float2(pa1.x, pa1.y);
            *(float2*)&a2[(kq * 2 + 9) * 128 + r2] = make_float2(pa1.z, pa1.w);
            *(float2*)&w2[(kq * 2    ) * 128 + r2] = make_float2(pw0.x, pw0.y);
            *(float2*)&w2[(kq * 2 + 1) * 128 + r2] = make_float2(pw0.z, pw0.w);
            *(float2*)&w2[(kq * 2 + 8) * 128 + r2] = make_float2(pw1.x, pw1.y);
            *(float2*)&w2[(kq * 2 + 9) * 128 + r2] = make_float2(pw1.z, pw1.w);
        }
        __syncthreads();
        buf ^= 1;
    }

    float cacc[4][4];
    #pragma unroll
    for (int i = 0; i < 4; i++)
        #pragma unroll
        for (int j = 0; j < 4; j++) {
            float2 u = f2unpack(acc[i][j]);
            cacc[i][j] = u.x + u.y;
        }

    #pragma unroll
    for (int i = 0; i < 4; i++) {
        float* crow = C + (ty * 4 + i) * ldc;
        #pragma unroll
        for (int j = 0; j < 4; j++) {
            int n = (tx << 2) + j;
            if (n < nValid) crow[n] = cacc[i][j];
        }
    }

    if (vout) {
        float* red = sm;
        #pragma unroll
        for (int j = 0; j < 4; j++) {
            float s = cacc[0][j] + cacc[1][j] + cacc[2][j] + cacc[3][j];
            red[ty * 64 + (tx << 2) + j] = s;
        }
        __syncthreads();
        if (tid < 64) {
            float s = 0.f;
            #pragma unroll
            for (int r = 0; r < 16; r++) s += red[r * 64 + tid];
            vout[tid] = s;
        }
        __syncthreads();
    }
}

// ---------------- persistent kernel (2 blocks/SM) ----------------
__global__ void __launch_bounds__(256, 2) ggnn_persistent(
    const float* __restrict__ input, const float* __restrict__ matrix,
    const float* __restrict__ w3w, const float* __restrict__ b3w,
    const float* __restrict__ w3u, const float* __restrict__ b3u,
    const float* __restrict__ w4w, const float* __restrict__ b4w,
    const float* __restrict__ w5w, const float* __restrict__ b5w,
    const float* __restrict__ w5u, const float* __restrict__ b5u,
    const float* __restrict__ wo,  const float* __restrict__ bo,
    const float* __restrict__ wc,  const float* __restrict__ bc,
    float* __restrict__ out)
{
    __shared__ __align__(16) float sm[8192];   // 32 KB
    __shared__ float s_red[16];
    __shared__ float s_s1, s_s2;

    const int NB = gridDim.x;
    const int bid = blockIdx.x;
    const int tid = threadIdx.x;
    const int gstride = NB * 256;
    unsigned epoch = 0;

    // ---- s1 (colsum of matrix col 0), s2 (rowsum of matrix row 0) ----
    {
        float a = (tid < CCLS) ? matrix[tid * CCLS] : 0.f;
        float b = (tid < CCLS) ? matrix[tid] : 0.f;
        #pragma unroll
        for (int off = 16; off; off >>= 1) {
            a += __shfl_xor_sync(0xffffffffu, a, off);
            b += __shfl_xor_sync(0xffffffffu, b, off);
        }
        if ((tid & 31) == 0) { s_red[tid >> 5] = a; s_red[8 + (tid >> 5)] = b; }
        __syncthreads();
        if (tid == 0) {
            float sa = 0.f, sb = 0.f;
            #pragma unroll
            for (int w = 0; w < 8; w++) { sa += s_red[w]; sb += s_red[8 + w]; }
            s_s1 = sa; s_s2 = sb;
        }
        __syncthreads();
    }
    const float s1 = s_s1, s2 = s_s2;

    // ---- setup ----
    for (int u = bid * 256 + tid; u < 3 * DH * DH / 4; u += gstride) {
        int which = u >> 16;
        int r = u & 65535;
        int o = r >> 7;
        int d4 = (r & 127) << 2;
        const float* w = (which == 0) ? w3w : (which == 1) ? w4w : w5w;
        float4 lo = *(const float4*)(w + o * 2 * DH + d4);
        float4 hi = *(const float4*)(w + o * 2 * DH + DH + d4);
        float4 e;
        e.x = s1 * lo.x + s2 * hi.x; e.y = s1 * lo.y + s2 * hi.y;
        e.z = s1 * lo.z + s2 * hi.z; e.w = s1 * lo.w + s2 * hi.w;
        *(float4*)&g_weff[which][o * DH + d4] = e;
    }
    for (int u = bid * 256 + tid; u < NOBJ * DH / 4; u += gstride)
        ((float4*)g_h)[u] = ((const float4*)input)[u];
    // wcred: unit = (c, quarter) -> 604 units
    for (int unit = bid; unit < CCLS * 4; unit += NB) {
        int c = unit >> 2;
        int d0 = (unit & 3) * 128;
        const float* base = wc + (size_t)c * (CCLS * DH) + d0;
        if (tid < 128) {
            int d = tid;
            float s = 0.f;
            #pragma unroll 4
            for (int c2 = 0; c2 < CCLS; c2++) s += base[c2 * DH + d];
            g_wcred[c * DH + d0 + d] = s;
        }
    }
    gsync(epoch, NB);

    // ---- T steps ----
    for (int t = 0; t < TSTEPS; t++) {
        // GEMM1: Gp[kc] = h[:,k0:k0+256] @ Wcat[:,k0:k0+256]^T, 256 tiles
        for (int tile = bid; tile < 256; tile += NB) {
            int kc = tile & 1, mt = (tile >> 1) & 3, nt = tile >> 3;
            int m0 = mt * 64, n0 = nt * 64, k0 = kc * 256;
            int z = n0 >> 9;
            const float* Wp = (z < 3) ? &g_weff[z][(n0 & 511) * DH]
                                      : (w3u + (n0 & 511) * DH);
            gemm_tile(g_h + m0 * DH + k0, DH, Wp + k0, DH, 256, 64,
                      g_Gp[kc] + m0 * GW + n0, GW, &g_vpart[kc * 4 + mt][n0], sm);
        }
        gsync(epoch, NB);

        // gate1
        for (int i = bid * 256 + tid; i < NOBJ * DH; i += gstride) {
            int o = i & (DH - 1);
            float v0 = 0.f, v1 = 0.f;
            #pragma unroll
            for (int p = 0; p < 8; p++) { v0 += g_vpart[p][o]; v1 += g_vpart[p][512 + o]; }
            int base = (i >> 9) * GW;
            float G0 = g_Gp[0][base + o] + g_Gp[1][base + o];
            float G1 = g_Gp[0][base + 512 + o] + g_Gp[1][base + 512 + o];
            float G3 = g_Gp[0][base + 1536 + o] + g_Gp[1][base + 1536 + o];
            float bu = b3u[o] + G3;
            float z = sigmoidf_(v0 - G0 + b3w[o] + bu);
            float r = sigmoidf_(v1 - G1 + b4w[o] + bu);
            g_zv[i] = z;
            g_rvh[i] = r * g_h[i];
        }
        gsync(epoch, NB);

        // GEMM2: g5u = rvh @ w5u^T, K-split x8 -> 256 tiles
        for (int tile = bid; tile < 256; tile += NB) {
            int kc = tile & 7, mt = (tile >> 3) & 3, nt = tile >> 5;
            int m0 = mt * 64, n0 = nt * 64, k0 = kc * 64;
            gemm_tile(g_rvh + m0 * DH + k0, DH, w5u + n0 * DH + k0, DH, 64, 64,
                      g_part[kc] + m0 * DH + n0, DH, nullptr, sm);
        }
        gsync(epoch, NB);

        // gate2
        for (int i = bid * 256 + tid; i < NOBJ * DH; i += gstride) {
            int o = i & (DH - 1);
            float v2 = 0.f;
            #pragma unroll
            for (int p = 0; p < 8; p++) v2 += g_vpart[p][1024 + o];
            int base = (i >> 9) * GW;
            float G2 = g_Gp[0][base + 1024 + o] + g_Gp[1][base + 1024 + o];
            float g5 = 0.f;
            #pragma unroll
            for (int p = 0; p < 8; p++) g5 += g_part[p][i];
            float hv = tanhf_(v2 - G2 + b5w[o] + g5 + b5u[o]);
            float z = g_zv[i];
            g_h[i] = (1.f - z) * g_h[i] + z * hv;
        }
        gsync(epoch, NB);
    }

    // GEMM3: pre-out = h@wo[:,:512]^T + input@wo[:,512:]^T, K-split x8 -> 256 tiles
    for (int tile = bid; tile < 256; tile += NB) {
        int kc = tile & 7, mt = (tile >> 3) & 3, nt = tile >> 5;
        int m0 = mt * 64, n0 = nt * 64;
        const float* Ap; const float* Wp;
        if (kc < 4) { Ap = g_h + m0 * DH + kc * 128;           Wp = wo + n0 * (2 * DH) + kc * 128; }
        else        { Ap = input + m0 * DH + (kc - 4) * 128;   Wp = wo + n0 * (2 * DH) + 512 + (kc - 4) * 128; }
        gemm_tile(Ap, DH, Wp, 2 * DH, 128, 64,
                  g_part[kc] + m0 * DH + n0, DH, nullptr, sm);
    }
    gsync(epoch, NB);

    // out2 = relu(sum partials + bo)
    for (int i = bid * 256 + tid; i < NOBJ * DH; i += gstride) {
        int o = i & (DH - 1);
        float s = bo[o];
        #pragma unroll
        for (int p = 0; p < 8; p++) s += g_part[p][i];
        g_out2[i] = fmaxf(s, 0.f);
    }
    gsync(epoch, NB);

    // GEMM4: out2 @ wcred^T (256 x 151), K-split x8 -> 96 tiles
    for (int tile = bid; tile < 96; tile += NB) {
        int nt = tile % 3; int mt = (tile / 3) & 3; int kc = tile / 12;
        int m0 = mt * 64, n0 = nt * 64, k0 = kc * 64;
        int nv = CCLS - n0; if (nv > 64) nv = 64;
        gemm_tile(g_out2 + m0 * DH + k0, DH, g_wcred + n0 * DH + k0, DH, 64, nv,
                  g_pc[kc] + m0 * 160 + n0, 160, nullptr, sm);
    }
    gsync(epoch, NB);

    // final: out = sum partials + bc
    for (int i = bid * 256 + tid; i < NOBJ * CCLS; i += gstride) {
        int n = i / CCLS, c = i - n * CCLS;
        float s = bc[c];
        #pragma unroll
        for (int kc = 0; kc < 8; kc++) s += g_pc[kc][n * 160 + c];
        out[i] = s;
    }
}

// ---------------- host launcher ----------------
extern "C" void kernel_launch(void* const* d_in, const int* in_sizes, int n_in,
                              void* d_out, int out_size) {
    (void)in_sizes; (void)n_in; (void)out_size;
    const float* input  = (const float*)d_in[0];
    const float* matrix = (const float*)d_in[1];
    const float* w3w = (const float*)d_in[2];
    const float* b3w = (const float*)d_in[3];
    const float* w3u = (const float*)d_in[4];
    const float* b3u = (const float*)d_in[5];
    const float* w4w = (const float*)d_in[6];
    const float* b4w = (const float*)d_in[7];
    // d_in[8] = w4u, d_in[9] = b4u : unused (faithful to reference bug)
    const float* w5w = (const float*)d_in[10];
    const float* b5w = (const float*)d_in[11];
    const float* w5u = (const float*)d_in[12];
    const float* b5u = (const float*)d_in[13];
    const float* wo  = (const float*)d_in[14];
    const float* bo  = (const float*)d_in[15];
    const float* wc  = (const float*)d_in[16];
    const float* bc  = (const float*)d_in[17];
    float* out = (float*)d_out;

    // Residency-proven block count (software barrier must not outnumber resident blocks)
    int sms = 0;
    cudaDeviceGetAttribute(&sms, cudaDevAttrMultiProcessorCount, 0);
    if (sms <= 0) sms = 1;
    int perSM = 0;
    cudaOccupancyMaxActiveBlocksPerMultiprocessor(&perSM, ggnn_persistent, 256, 0);
    if (perSM <= 0) perSM = 1;
    long long cap = (long long)sms * (long long)perSM;
    int NB = (cap < 296) ? (int)cap : 296;
    if (NB < 1) NB = 1;

    k_reset<<<1, 1>>>();
    ggnn_persistent<<<NB, 256>>>(input, matrix, w3w, b3w, w3u, b3u, w4w, b4w,
                                 w5w, b5w, w5u, b5u, wo, bo, wc, bc, out);
}

// round 9
// speedup vs baseline: 1.1286x; 1.0910x over previous
#include <cuda_runtime.h>
#include <math.h>

#define NOBJ 256
#define CCLS 151
#define DH   512
#define GW   2048          // G width: [weff3 | weff4(w4w) | weff5(w5w) | w3u]
#define TSTEPS 3

#define SROW 132           // padded smem row stride (floats) per k-row
#define ABUF 2112          // 16 * SROW
#define BUFSZ 4224         // A+W one stage

// ---------------- device scratch ----------------
__device__ float g_h[NOBJ * DH];
__device__ float g_weff[3][DH * DH];
__device__ float g_Gp[8][NOBJ * GW];     // GEMM1 K-split partials
__device__ float g_vpart[16][GW];        // column-sum partials [kc*2+mt]
__device__ float g_zv[NOBJ * DH];
__device__ float g_rvh[NOBJ * DH];
__device__ float g_part[16][NOBJ * DH];  // K-split partials (GEMM2 / GEMM3)
__device__ float g_out2[NOBJ * DH];
__device__ float g_wcred[CCLS * DH];
__device__ float g_pc[16][NOBJ * 160];   // classifier K-split partials (ldc=160)
__device__ unsigned g_bar;

__global__ void k_reset() { g_bar = 0u; }

// ---------------- f32x2 helpers ----------------
__device__ __forceinline__ unsigned long long f2pack(float lo, float hi) {
    unsigned long long r;
    asm("mov.b64 %0, {%1, %2};" : "=l"(r) : "r"(__float_as_uint(lo)), "r"(__float_as_uint(hi)));
    return r;
}
__device__ __forceinline__ void ffma2(unsigned long long& d, unsigned long long a, unsigned long long b) {
    asm("fma.rn.f32x2 %0, %1, %2, %0;" : "+l"(d) : "l"(a), "l"(b));
}
__device__ __forceinline__ float2 f2unpack(unsigned long long v) {
    unsigned lo, hi;
    asm("mov.b64 {%0, %1}, %2;" : "=r"(lo), "=r"(hi) : "l"(v));
    return make_float2(__uint_as_float(lo), __uint_as_float(hi));
}

__device__ __forceinline__ float sigmoidf_(float x) { return 1.f / (1.f + __expf(-x)); }
__device__ __forceinline__ float tanhf_(float x) { return 1.f - 2.f / (__expf(2.f * x) + 1.f); }

// ---------------- global barrier ----------------
__device__ __forceinline__ void gsync(unsigned& epoch, int nb) {
    __syncthreads();
    if (threadIdx.x == 0) {
        __threadfence();
        atomicAdd(&g_bar, 1u);
        epoch += (unsigned)nb;
        while (*(volatile unsigned*)&g_bar < epoch) { __nanosleep(32); }
        __threadfence();
    }
    __syncthreads();
}

// ---------------- 128x128 tile GEMM: C = A[128,kLen] @ W[nValid<=128,kLen]^T -------------
// Thread org: 256 thr, 8 warps (wr = warp&1, wcl = warp>>2... wcl = warp>>1).
// warp tile 64x32, thread tile 8x8 (lanes: lr = lane&7 rows, lc = lane>>3 cols).
// smem: k-major transposed tiles, row stride SROW, double buffered.
__device__ __forceinline__ void gemm128(
    const float* __restrict__ A, int lda,
    const float* __restrict__ W, int ldw,
    int kLen, int nValid,
    float* __restrict__ C, int ldc,
    float* __restrict__ vout,
    float* __restrict__ sm)
{
    const int tid = threadIdx.x;
    const int warp = tid >> 5, lane = tid & 31;
    const int wr = warp & 1, wcl = warp >> 1;
    const int lr = lane & 7, lc = lane >> 3;
    const int m_lo = tid >> 2, m_hi = m_lo + 64, kg = tid & 3;
    const int mloc = wr * 64 + lr * 8;
    const int nloc = wcl * 32 + lc * 8;
    const int nCh = kLen >> 4;

    unsigned long long d[8][4];
    #pragma unroll
    for (int i = 0; i < 8; i++)
        #pragma unroll
        for (int j = 0; j < 4; j++) d[i][j] = 0ull;

    const float4 z4 = make_float4(0.f, 0.f, 0.f, 0.f);
    const float* Alo = A + m_lo * lda + kg * 4;
    const float* Ahi = A + m_hi * lda + kg * 4;
    const float* Wlo = W + m_lo * ldw + kg * 4;
    const float* Whi = W + m_hi * ldw + kg * 4;
    const bool okLo = m_lo < nValid, okHi = m_hi < nValid;

    float4 pA0 = *(const float4*)Alo;
    float4 pA1 = *(const float4*)Ahi;
    float4 pW0 = okLo ? *(const float4*)Wlo : z4;
    float4 pW1 = okHi ? *(const float4*)Whi : z4;

    // store chunk 0 into buffer 0 (transpose to k-major)
    {
        float* Ab = sm;
        float* Wb = sm + ABUF;
        int kb = kg * 4;
        Ab[(kb + 0) * SROW + m_lo] = pA0.x; Ab[(kb + 1) * SROW + m_lo] = pA0.y;
        Ab[(kb + 2) * SROW + m_lo] = pA0.z; Ab[(kb + 3) * SROW + m_lo] = pA0.w;
        Ab[(kb + 0) * SROW + m_hi] = pA1.x; Ab[(kb + 1) * SROW + m_hi] = pA1.y;
        Ab[(kb + 2) * SROW + m_hi] = pA1.z; Ab[(kb + 3) * SROW + m_hi] = pA1.w;
        Wb[(kb + 0) * SROW + m_lo] = pW0.x; Wb[(kb + 1) * SROW + m_lo] = pW0.y;
        Wb[(kb + 2) * SROW + m_lo] = pW0.z; Wb[(kb + 3) * SROW + m_lo] = pW0.w;
        Wb[(kb + 0) * SROW + m_hi] = pW1.x; Wb[(kb + 1) * SROW + m_hi] = pW1.y;
        Wb[(kb + 2) * SROW + m_hi] = pW1.z; Wb[(kb + 3) * SROW + m_hi] = pW1.w;
    }
    __syncthreads();

    for (int c = 0; c < nCh; c++) {
        if (c + 1 < nCh) {
            int ko = (c + 1) * 16;
            pA0 = *(const float4*)(Alo + ko);
            pA1 = *(const float4*)(Ahi + ko);
            pW0 = okLo ? *(const float4*)(Wlo + ko) : z4;
            pW1 = okHi ? *(const float4*)(Whi + ko) : z4;
        }
        const float* Ab = sm + (c & 1) * BUFSZ;
        const float* Wb = Ab + ABUF;
        #pragma unroll
        for (int k = 0; k < 16; k++) {
            const float* ak = Ab + k * SROW + mloc;
            const float* bk = Wb + k * SROW + nloc;
            float4 a0 = *(const float4*)ak;
            float4 a1 = *(const float4*)(ak + 4);
            float4 b0 = *(const float4*)bk;
            float4 b1 = *(const float4*)(bk + 4);
            unsigned long long bp0 = f2pack(b0.x, b0.y), bp1 = f2pack(b0.z, b0.w);
            unsigned long long bp2 = f2pack(b1.x, b1.y), bp3 = f2pack(b1.z, b1.w);
            unsigned long long aa;
            aa = f2pack(a0.x, a0.x);
            ffma2(d[0][0], aa, bp0); ffma2(d[0][1], aa, bp1); ffma2(d[0][2], aa, bp2); ffma2(d[0][3], aa, bp3);
            aa = f2pack(a0.y, a0.y);
            ffma2(d[1][0], aa, bp0); ffma2(d[1][1], aa, bp1); ffma2(d[1][2], aa, bp2); ffma2(d[1][3], aa, bp3);
            aa = f2pack(a0.z, a0.z);
            ffma2(d[2][0], aa, bp0); ffma2(d[2][1], aa, bp1); ffma2(d[2][2], aa, bp2); ffma2(d[2][3], aa, bp3);
            aa = f2pack(a0.w, a0.w);
            ffma2(d[3][0], aa, bp0); ffma2(d[3][1], aa, bp1); ffma2(d[3][2], aa, bp2); ffma2(d[3][3], aa, bp3);
            aa = f2pack(a1.x, a1.x);
            ffma2(d[4][0], aa, bp0); ffma2(d[4][1], aa, bp1); ffma2(d[4][2], aa, bp2); ffma2(d[4][3], aa, bp3);
            aa = f2pack(a1.y, a1.y);
            ffma2(d[5][0], aa, bp0); ffma2(d[5][1], aa, bp1); ffma2(d[5][2], aa, bp2); ffma2(d[5][3], aa, bp3);
            aa = f2pack(a1.z, a1.z);
            ffma2(d[6][0], aa, bp0); ffma2(d[6][1], aa, bp1); ffma2(d[6][2], aa, bp2); ffma2(d[6][3], aa, bp3);
            aa = f2pack(a1.w, a1.w);
            ffma2(d[7][0], aa, bp0); ffma2(d[7][1], aa, bp1); ffma2(d[7][2], aa, bp2); ffma2(d[7][3], aa, bp3);
        }
        if (c + 1 < nCh) {
            float* Ab2 = sm + ((c + 1) & 1) * BUFSZ;
            float* Wb2 = Ab2 + ABUF;
            int kb = kg * 4;
            Ab2[(kb + 0) * SROW + m_lo] = pA0.x; Ab2[(kb + 1) * SROW + m_lo] = pA0.y;
            Ab2[(kb + 2) * SROW + m_lo] = pA0.z; Ab2[(kb + 3) * SROW + m_lo] = pA0.w;
            Ab2[(kb + 0) * SROW + m_hi] = pA1.x; Ab2[(kb + 1) * SROW + m_hi] = pA1.y;
            Ab2[(kb + 2) * SROW + m_hi] = pA1.z; Ab2[(kb + 3) * SROW + m_hi] = pA1.w;
            Wb2[(kb + 0) * SROW + m_lo] = pW0.x; Wb2[(kb + 1) * SROW + m_lo] = pW0.y;
            Wb2[(kb + 2) * SROW + m_lo] = pW0.z; Wb2[(kb + 3) * SROW + m_lo] = pW0.w;
            Wb2[(kb + 0) * SROW + m_hi] = pW1.x; Wb2[(kb + 1) * SROW + m_hi] = pW1.y;
            Wb2[(kb + 2) * SROW + m_hi] = pW1.z; Wb2[(kb + 3) * SROW + m_hi] = pW1.w;
        }
        __syncthreads();
    }

    // unpack: d[i][j2] = (col 2*j2, col 2*j2+1)
    float cc[8][8];
    #pragma unroll
    for (int i = 0; i < 8; i++)
        #pragma unroll
        for (int j2 = 0; j2 < 4; j2++) {
            float2 u = f2unpack(d[i][j2]);
            cc[i][2 * j2] = u.x;
            cc[i][2 * j2 + 1] = u.y;
        }

    if (nloc + 8 <= nValid) {
        #pragma unroll
        for (int i = 0; i < 8; i++) {
            float* crow = C + (mloc + i) * ldc + nloc;
            *(float4*)crow = make_float4(cc[i][0], cc[i][1], cc[i][2], cc[i][3]);
            *(float4*)(crow + 4) = make_float4(cc[i][4], cc[i][5], cc[i][6], cc[i][7]);
        }
    } else {
        #pragma unroll
        for (int i = 0; i < 8; i++) {
            float* crow = C + (mloc + i) * ldc;
            #pragma unroll
            for (int j = 0; j < 8; j++)
                if (nloc + j < nValid) crow[nloc + j] = cc[i][j];
        }
    }

    if (vout) {
        float s[8];
        #pragma unroll
        for (int j = 0; j < 8; j++)
            s[j] = cc[0][j] + cc[1][j] + cc[2][j] + cc[3][j]
                 + cc[4][j] + cc[5][j] + cc[6][j] + cc[7][j];
        #pragma unroll
        for (int off = 1; off < 8; off <<= 1)
            #pragma unroll
            for (int j = 0; j < 8; j++)
                s[j] += __shfl_xor_sync(0xffffffffu, s[j], off);
        float* vred = sm + 2 * BUFSZ;
        if (lr == 0) {
            #pragma unroll
            for (int j = 0; j < 8; j++) vred[wr * 128 + nloc + j] = s[j];
        }
        __syncthreads();
        if (tid < 128) vout[tid] = vred[tid] + vred[128 + tid];
        __syncthreads();
    }
}

// ---------------- persistent kernel (2 blocks/SM) ----------------
__global__ void __launch_bounds__(256, 2) ggnn_persistent(
    const float* __restrict__ input, const float* __restrict__ matrix,
    const float* __restrict__ w3w, const float* __restrict__ b3w,
    const float* __restrict__ w3u, const float* __restrict__ b3u,
    const float* __restrict__ w4w, const float* __restrict__ b4w,
    const float* __restrict__ w5w, const float* __restrict__ b5w,
    const float* __restrict__ w5u, const float* __restrict__ b5u,
    const float* __restrict__ wo,  const float* __restrict__ bo,
    const float* __restrict__ wc,  const float* __restrict__ bc,
    float* __restrict__ out)
{
    __shared__ __align__(16) float sm[2 * BUFSZ + 256];
    __shared__ float s_red[16];
    __shared__ float s_s1, s_s2;

    const int NB = gridDim.x;
    const int bid = blockIdx.x;
    const int tid = threadIdx.x;
    const int gstride = NB * 256;
    unsigned epoch = 0;

    // ---- s1 (colsum of matrix col 0), s2 (rowsum of matrix row 0) ----
    {
        float a = (tid < CCLS) ? matrix[tid * CCLS] : 0.f;
        float b = (tid < CCLS) ? matrix[tid] : 0.f;
        #pragma unroll
        for (int off = 16; off; off >>= 1) {
            a += __shfl_xor_sync(0xffffffffu, a, off);
            b += __shfl_xor_sync(0xffffffffu, b, off);
        }
        if ((tid & 31) == 0) { s_red[tid >> 5] = a; s_red[8 + (tid >> 5)] = b; }
        __syncthreads();
        if (tid == 0) {
            float sa = 0.f, sb = 0.f;
            #pragma unroll
            for (int w = 0; w < 8; w++) { sa += s_red[w]; sb += s_red[8 + w]; }
            s_s1 = sa; s_s2 = sb;
        }
        __syncthreads();
    }
    const float s1 = s_s1, s2 = s_s2;

    // ---- setup ----
    for (int u = bid * 256 + tid; u < 3 * DH * DH / 4; u += gstride) {
        int which = u >> 16;
        int r = u & 65535;
        int o = r >> 7;
        int d4 = (r & 127) << 2;
        const float* w = (which == 0) ? w3w : (which == 1) ? w4w : w5w;
        float4 lo = *(const float4*)(w + o * 2 * DH + d4);
        float4 hi = *(const float4*)(w + o * 2 * DH + DH + d4);
        float4 e;
        e.x = s1 * lo.x + s2 * hi.x; e.y = s1 * lo.y + s2 * hi.y;
        e.z = s1 * lo.z + s2 * hi.z; e.w = s1 * lo.w + s2 * hi.w;
        *(float4*)&g_weff[which][o * DH + d4] = e;
    }
    for (int u = bid * 256 + tid; u < NOBJ * DH / 4; u += gstride)
        ((float4*)g_h)[u] = ((const float4*)input)[u];
    // wcred: unit = (c, half); 302 units, all 256 threads used
    for (int unit = bid; unit < CCLS * 2; unit += NB) {
        int c = unit >> 1;
        int d = (unit & 1) * 256 + tid;
        const float* base = wc + (size_t)c * (CCLS * DH) + d;
        float s = 0.f;
        #pragma unroll 4
        for (int c2 = 0; c2 < CCLS; c2++) s += base[c2 * DH];
        g_wcred[c * DH + d] = s;
    }
    gsync(epoch, NB);

    // ---- T steps ----
    for (int t = 0; t < TSTEPS; t++) {
        // GEMM1: Gp[kc] partials of h @ Wcat^T; 256 tiles (kc8 x mt2 x nt16)
        for (int tile = bid; tile < 256; tile += NB) {
            int kc = tile & 7, mt = (tile >> 3) & 1, nt = tile >> 4;
            int m0 = mt * 128, n0 = nt * 128, k0 = kc * 64;
            int z = n0 >> 9;
            const float* Wbase = (z < 3) ? (&g_weff[z][(n0 & 511) * DH])
                                         : (w3u + (n0 & 511) * DH);
            gemm128(g_h + m0 * DH + k0, DH, Wbase + k0, DH, 64, 128,
                    g_Gp[kc] + m0 * GW + n0, GW, &g_vpart[kc * 2 + mt][n0], sm);
        }
        gsync(epoch, NB);

        // gate1
        for (int i = bid * 256 + tid; i < NOBJ * DH; i += gstride) {
            int o = i & (DH - 1);
            float v0 = 0.f, v1 = 0.f;
            #pragma unroll
            for (int p = 0; p < 16; p++) { v0 += g_vpart[p][o]; v1 += g_vpart[p][512 + o]; }
            int base = (i >> 9) * GW;
            float G0 = 0.f, G1 = 0.f, G3 = 0.f;
            #pragma unroll
            for (int kc = 0; kc < 8; kc++) {
                G0 += g_Gp[kc][base + o];
                G1 += g_Gp[kc][base + 512 + o];
                G3 += g_Gp[kc][base + 1536 + o];
            }
            float bu = b3u[o] + G3;
            float z = sigmoidf_(v0 - G0 + b3w[o] + bu);
            float r = sigmoidf_(v1 - G1 + b4w[o] + bu);
            g_zv[i] = z;
            g_rvh[i] = r * g_h[i];
        }
        gsync(epoch, NB);

        // GEMM2: g5u = rvh @ w5u^T; 128 tiles (kc16 x mt2 x nt4)
        for (int tile = bid; tile < 128; tile += NB) {
            int kc = tile & 15, mt = (tile >> 4) & 1, nt = tile >> 5;
            int m0 = mt * 128, n0 = nt * 128, k0 = kc * 32;
            gemm128(g_rvh + m0 * DH + k0, DH, w5u + n0 * DH + k0, DH, 32, 128,
                    g_part[kc] + m0 * DH + n0, DH, nullptr, sm);
        }
        gsync(epoch, NB);

        // gate2
        for (int i = bid * 256 + tid; i < NOBJ * DH; i += gstride) {
            int o = i & (DH - 1);
            float v2 = 0.f;
            #pragma unroll
            for (int p = 0; p < 16; p++) v2 += g_vpart[p][1024 + o];
            int base = (i >> 9) * GW;
            float G2 = 0.f;
            #pragma unroll
            for (int kc = 0; kc < 8; kc++) G2 += g_Gp[kc][base + 1024 + o];
            float g5 = 0.f;
            #pragma unroll
            for (int p = 0; p < 16; p++) g5 += g_part[p][i];
            float hv = tanhf_(v2 - G2 + b5w[o] + g5 + b5u[o]);
            float z = g_zv[i];
            g_h[i] = (1.f - z) * g_h[i] + z * hv;
        }
        gsync(epoch, NB);
    }

    // GEMM3: pre-out = h@wo[:,:512]^T + input@wo[:,512:]^T; 128 tiles (kc16 x mt2 x nt4)
    for (int tile = bid; tile < 128; tile += NB) {
        int kc = tile & 15, mt = (tile >> 4) & 1, nt = tile >> 5;
        int m0 = mt * 128, n0 = nt * 128;
        const float* Ap; const float* Wp;
        if (kc < 8) { Ap = g_h + m0 * DH + kc * 64;           Wp = wo + n0 * (2 * DH) + kc * 64; }
        else        { Ap = input + m0 * DH + (kc - 8) * 64;   Wp = wo + n0 * (2 * DH) + 512 + (kc - 8) * 64; }
        gemm128(Ap, DH, Wp, 2 * DH, 64, 128,
                g_part[kc] + m0 * DH + n0, DH, nullptr, sm);
    }
    gsync(epoch, NB);

    // out2 = relu(sum partials + bo)
    for (int i = bid * 256 + tid; i < NOBJ * DH; i += gstride) {
        int o = i & (DH - 1);
        float s = bo[o];
        #pragma unroll
        for (int p = 0; p < 16; p++) s += g_part[p][i];
        g_out2[i] = fmaxf(s, 0.f);
    }
    gsync(epoch, NB);

    // GEMM4: out2 @ wcred^T (256 x 151); 64 tiles (kc16 x mt2 x nt2)
    for (int tile = bid; tile < 64; tile += NB) {
        int kc = tile & 15, mt = (tile >> 4) & 1, nt = tile >> 5;
        int m0 = mt * 128, n0 = nt * 128, k0 = kc * 32;
        int nv = CCLS - n0; if (nv > 128) nv = 128;
        gemm128(g_out2 + m0 * DH + k0, DH, g_wcred + n0 * DH + k0, DH, 32, nv,
                g_pc[kc] + m0 * 160 + n0, 160, nullptr, sm);
    }
    gsync(epoch, NB);

    // final: out = sum partials + bc
    for (int i = bid * 256 + tid; i < NOBJ * CCLS; i += gstride) {
        int n = i / CCLS, c = i - n * CCLS;
        float s = bc[c];
        #pragma unroll
        for (int kc = 0; kc < 16; kc++) s += g_pc[kc][n * 160 + c];
        out[i] = s;
    }
}

// ---------------- host launcher ----------------
extern "C" void kernel_launch(void* const* d_in, const int* in_sizes, int n_in,
                              void* d_out, int out_size) {
    (void)in_sizes; (void)n_in; (void)out_size;
    const float* input  = (const float*)d_in[0];
    const float* matrix = (const float*)d_in[1];
    const float* w3w = (const float*)d_in[2];
    const float* b3w = (const float*)d_in[3];
    const float* w3u = (const float*)d_in[4];
    const float* b3u = (const float*)d_in[5];
    const float* w4w = (const float*)d_in[6];
    const float* b4w = (const float*)d_in[7];
    // d_in[8] = w4u, d_in[9] = b4u : unused (faithful to reference bug)
    const float* w5w = (const float*)d_in[10];
    const float* b5w = (const float*)d_in[11];
    const float* w5u = (const float*)d_in[12];
    const float* b5u = (const float*)d_in[13];
    const float* wo  = (const float*)d_in[14];
    const float* bo  = (const float*)d_in[15];
    const float* wc  = (const float*)d_in[16];
    const float* bc  = (const float*)d_in[17];
    float* out = (float*)d_out;

    // Residency-proven block count (software barrier must not outnumber resident blocks)
    int sms = 0;
    cudaDeviceGetAttribute(&sms, cudaDevAttrMultiProcessorCount, 0);
    if (sms <= 0) sms = 1;
    int perSM = 0;
    cudaOccupancyMaxActiveBlocksPerMultiprocessor(&perSM, ggnn_persistent, 256,
                                                  (2 * BUFSZ + 256) * 0 /* static smem */);
    if (perSM <= 0) perSM = 1;
    long long cap = (long long)sms * (long long)perSM;
    int NB = (cap < 296) ? (int)cap : 296;
    if (NB < 1) NB = 1;

    k_reset<<<1, 1>>>();
    ggnn_persistent<<<NB, 256>>>(input, matrix, w3w, b3w, w3u, b3u, w4w, b4w,
                                 w5w, b5w, w5u, b5u, wo, bo, wc, bc, out);
}